// round 7
// baseline (speedup 1.0000x reference)
#include <cuda_runtime.h>
#include <math.h>

#define NUM_CITIES 88
#define NC4        22          // 88 / 4 float4 groups per row
#define NUM_YEARS  6
#define N_ROWS     200000

#define MAIN_BLOCK 352         // 22 * 16 -> total threads stay multiple of 22
#define MAIN_GRID  592         // one wave at 4 blocks/SM (or 1.3 waves at 3)

// Scratch accumulators. Zero at module load; last block resets them each
// launch so every graph replay starts clean.
__device__ float g_colsum[NUM_CITIES];
__device__ float g_scalar;
__device__ unsigned int g_count;

__device__ __forceinline__ void body(const float4 g, const float4 d,
                                     const float4 w,
                                     float& c0, float& c1, float& c2, float& c3,
                                     float& s)
{
    c0 += fabsf(g.x); c1 += fabsf(g.y);
    c2 += fabsf(g.z); c3 += fabsf(g.w);

    float r0 = fmaf(-w.x, d.x, g.x);
    float r1 = fmaf(-w.y, d.y, g.y);
    float r2 = fmaf(-w.z, d.z, g.z);
    float r3 = fmaf(-w.w, d.w, g.w);
    s += 100.0f * (r0*r0 + r1*r1 + r2*r2 + r3*r3);

    s += 0.01f * (w.x*w.x + w.y*w.y + w.z*w.z + w.w*w.w);

    s += 100.0f * (fminf(g.x, 0.f) + fminf(g.y, 0.f)
                 + fminf(g.z, 0.f) + fminf(g.w, 0.f));
}

__global__ __launch_bounds__(MAIN_BLOCK)
void fused_loss_kernel(const float4* __restrict__ G4,
                       const float4* __restrict__ D4,
                       const float4* __restrict__ W4,
                       const float*  __restrict__ U,
                       const float*  __restrict__ OUT,
                       float* __restrict__ out)
{
    const int tid    = blockIdx.x * MAIN_BLOCK + threadIdx.x;
    const int total  = gridDim.x * MAIN_BLOCK;          // multiple of 22
    const int lanes  = total / NC4;                     // row-stride lanes
    const int cg     = tid % NC4;                       // fixed column group
    const int lane   = tid / NC4;

    float c0 = 0.f, c1 = 0.f, c2 = 0.f, c3 = 0.f;       // |G| column partials
    float s  = 0.f;                                     // scalar loss partial

    // Term 1: ||U[:, :5] - out[:, :5]||_F^2  (9.6 MB)
    for (int r = tid; r < N_ROWS; r += total) {
        const float* u = U   + r * NUM_YEARS;
        const float* o = OUT + r * NUM_YEARS;
        #pragma unroll
        for (int j = 0; j < NUM_YEARS - 1; j++) {
            float d = u[j] - o[j];
            s += d * d;
        }
    }

    // Main stream: G, D, w (211 MB). Unrolled x2 with all 6 LDG.128 batched
    // up front (MLP_p1 = 6) so each warp keeps 768B outstanding.
    int r = lane;
    const int step2 = 2 * lanes;
    for (; r + lanes < N_ROWS; r += step2) {
        const int i0 = r * NC4 + cg;
        const int i1 = i0 + lanes * NC4;
        float4 g0 = __ldcs(&G4[i0]);
        float4 d0 = __ldcs(&D4[i0]);
        float4 w0 = __ldcs(&W4[i0]);
        float4 g1 = __ldcs(&G4[i1]);
        float4 d1 = __ldcs(&D4[i1]);
        float4 w1 = __ldcs(&W4[i1]);

        body(g0, d0, w0, c0, c1, c2, c3, s);
        body(g1, d1, w1, c0, c1, c2, c3, s);
    }
    if (r < N_ROWS) {
        const int i0 = r * NC4 + cg;
        float4 g0 = __ldcs(&G4[i0]);
        float4 d0 = __ldcs(&D4[i0]);
        float4 w0 = __ldcs(&W4[i0]);
        body(g0, d0, w0, c0, c1, c2, c3, s);
    }

    // --- block-level reduction ---
    __shared__ float scol[NUM_CITIES];
    __shared__ float swarp[MAIN_BLOCK / 32];
    __shared__ unsigned int is_last;

    if (threadIdx.x < NUM_CITIES) scol[threadIdx.x] = 0.0f;
    __syncthreads();

    atomicAdd(&scol[cg * 4 + 0], c0);
    atomicAdd(&scol[cg * 4 + 1], c1);
    atomicAdd(&scol[cg * 4 + 2], c2);
    atomicAdd(&scol[cg * 4 + 3], c3);

    #pragma unroll
    for (int off = 16; off > 0; off >>= 1)
        s += __shfl_xor_sync(0xFFFFFFFF, s, off);
    if ((threadIdx.x & 31) == 0) swarp[threadIdx.x >> 5] = s;
    __syncthreads();

    // --- grid-level accumulation ---
    if (threadIdx.x < NUM_CITIES)
        atomicAdd(&g_colsum[threadIdx.x], scol[threadIdx.x]);

    if (threadIdx.x == 0) {
        float bs = 0.f;
        #pragma unroll
        for (int wv = 0; wv < MAIN_BLOCK / 32; wv++) bs += swarp[wv];
        atomicAdd(&g_scalar, bs);
    }

    // --- last-block finalize ---
    __threadfence();
    __syncthreads();
    if (threadIdx.x == 0)
        is_last = (atomicAdd(&g_count, 1u) == (unsigned)(gridDim.x - 1));
    __syncthreads();
    if (!is_last) return;

    __threadfence();   // acquire: all blocks' atomics visible

    __shared__ float sh[128];
    int t = threadIdx.x;
    if (t < 128) {
        float v = 0.0f;
        if (t < NUM_CITIES) {
            v = logf(*((volatile float*)&g_colsum[t]));
            *((volatile float*)&g_colsum[t]) = 0.0f;   // reset for next replay
        }
        sh[t] = v;
    }
    __syncthreads();
    #pragma unroll
    for (int off = 64; off > 0; off >>= 1) {
        if (t < off) sh[t] += sh[t + off];
        __syncthreads();
    }
    if (t == 0) {
        float sc = *((volatile float*)&g_scalar);
        out[0] = sc + 1.0e-4f * sh[0];                 // stddeve^2 = 1e-4
        *((volatile float*)&g_scalar) = 0.0f;
        g_count = 0u;
    }
}

extern "C" void kernel_launch(void* const* d_in, const int* in_sizes, int n_in,
                              void* d_out, int out_size)
{
    // metadata order: G, out, U, V, D, w   (V unused by the loss)
    const float4* G4  = (const float4*)d_in[0];
    const float*  OUT = (const float*) d_in[1];
    const float*  U   = (const float*) d_in[2];
    const float4* D4  = (const float4*)d_in[4];
    const float4* W4  = (const float4*)d_in[5];
    float* out = (float*)d_out;

    fused_loss_kernel<<<MAIN_GRID, MAIN_BLOCK>>>(G4, D4, W4, U, OUT, out);
}